// round 14
// baseline (speedup 1.0000x reference)
#include <cuda_runtime.h>
#include <cuda_fp16.h>
#include <cstdint>

#define B_ 32
#define C_ 128
#define H_ 128
#define W_ 128
#define K_ 4
#define O_ 128
#define RS_ 9
#define NCTA 148
#define TILES2 (B_ * (H_ / 2))   // 2048 two-row tiles

// ---------------- scratch ----------------
__device__ float  g_pooled[B_ * C_];                         // atomic accum, zeroed per call
__device__ float  g_attn[B_ * K_];
__device__ float  g_aggb[B_ * O_];
__device__ __half g_aggw16[(size_t)B_ * RS_ * O_ * C_];      // [b][rs][o][c]
__device__ __half g_xT[(size_t)B_ * H_ * W_ * C_];           // [b][y][p][c] NHWC fp16
__device__ unsigned g_barcnt = 0;                            // monotonic, replay-safe

// ---------------- helpers ----------------
__device__ __forceinline__ uint32_t smem_u32(const void* p) {
    uint32_t a;
    asm("{ .reg .u64 t; cvta.to.shared.u64 t, %1; cvt.u32.u64 %0, t; }" : "=r"(a) : "l"(p));
    return a;
}
__device__ __forceinline__ void cp16(uint32_t dst, const void* src, int srcsize) {
    asm volatile("cp.async.cg.shared.global [%0], [%1], 16, %2;"
                 :: "r"(dst), "l"(src), "r"(srcsize) : "memory");
}
#define CP_COMMIT() asm volatile("cp.async.commit_group;" ::: "memory")
#define CP_WAIT(n)  asm volatile("cp.async.wait_group %0;" :: "n"(n) : "memory")

__device__ __forceinline__ void ldmat_x4(uint32_t* r, uint32_t addr) {
    asm volatile("ldmatrix.sync.aligned.m8n8.x4.shared.b16 {%0,%1,%2,%3}, [%4];"
                 : "=r"(r[0]), "=r"(r[1]), "=r"(r[2]), "=r"(r[3]) : "r"(addr));
}
__device__ __forceinline__ void mma16816(float* c, const uint32_t* a, const uint32_t* b) {
    asm volatile("mma.sync.aligned.m16n8k16.row.col.f32.f16.f16.f32 "
                 "{%0,%1,%2,%3}, {%4,%5,%6,%7}, {%8,%9}, {%0,%1,%2,%3};"
                 : "+f"(c[0]), "+f"(c[1]), "+f"(c[2]), "+f"(c[3])
                 : "r"(a[0]), "r"(a[1]), "r"(a[2]), "r"(a[3]), "r"(b[0]), "r"(b[1]));
}

// Replay-safe global barrier (grid = NCTA <= SM count -> co-resident).
__device__ __forceinline__ void global_bar() {
    __syncthreads();
    if (threadIdx.x == 0) {
        __threadfence();
        unsigned old = atomicAdd(&g_barcnt, 1u);
        unsigned target = old - (old % NCTA) + NCTA;
        while ((int)(atomicAdd(&g_barcnt, 0u) - target) < 0) {}
        __threadfence();
    }
    __syncthreads();
}

// ---------------- conv smem layout ----------------
#define A_STRIDE 272
#define A_BYTES  (128 * A_STRIDE)            // 34816
#define SM_B_OFF (2 * A_BYTES)               // 69632
#define B_ROW    (130 * A_STRIDE)            // 35360
#define SMEM_CONV (SM_B_OFF + 4 * B_ROW)     // 211072

__device__ __forceinline__ void stage_A(uint32_t sb, int buf, const __half* __restrict__ asrc,
                                        int tid) {
    uint32_t dst = sb + buf * A_BYTES;
    #pragma unroll
    for (int k = 0; k < 4; k++) {
        int i = tid + k * 512;
        int o = i >> 4, ch = i & 15;
        cp16(dst + o * A_STRIDE + ch * 16, asrc + (size_t)o * C_ + ch * 8, 16);
    }
}
__device__ __forceinline__ void stage_Brow(uint32_t sb, int b, int ry, int tid) {
    int slot = (ry + 4) & 3;
    bool rok = (ry >= 0) & (ry < H_);
    const __half* rbase = g_xT + ((size_t)b * H_ + (rok ? ry : 0)) * W_ * C_;
    uint32_t dst = sb + SM_B_OFF + slot * B_ROW;
    for (int i = tid; i < 2080; i += 512) {
        int p = i >> 4, ch = i & 15;
        int px = p - 1;
        bool ok = rok & (px >= 0) & (px < W_);
        cp16(dst + p * A_STRIDE + ch * 16, rbase + (size_t)(ok ? px : 0) * C_ + ch * 8,
             ok ? 16 : 0);
    }
}

// ================= MEGAKERNEL v2 =================
__global__ void __launch_bounds__(512, 1) mega(const float* __restrict__ x,
                                               const float* __restrict__ w1,
                                               const float* __restrict__ b1,
                                               const float* __restrict__ w2,
                                               const float* __restrict__ b2,
                                               const float* __restrict__ bias,
                                               const float* __restrict__ weight,
                                               float* __restrict__ out) {
    extern __shared__ char smem[];
    const uint32_t sb = smem_u32(smem);
    const int tid = threadIdx.x, lane = tid & 31, wid = tid >> 5;   // 16 warps
    const int cid = blockIdx.x;

    // ---- zero pooled accumulator (replay-safe), then barrier ----
    if (cid == 0) {
        for (int i = tid; i < B_ * C_; i += 512) g_pooled[i] = 0.f;
    }
    global_bar();

    // ========== phase 0: transpose + pooling, warp-independent slices ==========
    // 32768 warp-slices: slice = (row 0..4095, sub 0..7); sub -> (c0, p0).
    {
        __half* s = (__half*)smem + (size_t)wid * (64 * 33);   // 4224 B per warp
        const int wgid = cid * 16 + wid;                        // 0..2367
        const int cl = lane >> 3;            // 0..3
        const int pxl4 = (lane & 7) * 4;     // 0,4,..,28
        const int c8 = (lane & 7) * 8;
        const int pxg = lane >> 3;

        for (int it = 0; it < 14; it++) {
            int sid = wgid + 2368 * it;
            if (sid >= 32768) break;
            int row = sid >> 3, sub = sid & 7;
            int b = row >> 7, y = row & 127;
            int c0 = (sub & 1) * 64, p0 = (sub >> 1) * 32;

            // load 64c x 32px: 16 LDG.128 per lane-group, scalar STS (stride 33, conflict-free)
            #pragma unroll
            for (int i = 0; i < 16; i++) {
                int c_local = i * 4 + cl;
                float4 v = *(const float4*)(x + (((size_t)b * C_ + c0 + c_local) * H_ + y) * W_ + p0 + pxl4);
                __half* d = s + c_local * 33 + pxl4;
                d[0] = __float2half_rn(v.x);
                d[1] = __float2half_rn(v.y);
                d[2] = __float2half_rn(v.z);
                d[3] = __float2half_rn(v.w);
            }
            __syncwarp();

            float pacc[8];
            #pragma unroll
            for (int j = 0; j < 8; j++) pacc[j] = 0.f;
            #pragma unroll
            for (int i = 0; i < 8; i++) {
                int pixl = pxg + 4 * i;
                uint32_t pk[4];
                #pragma unroll
                for (int j = 0; j < 4; j++) {
                    __half h0 = s[(c8 + 2 * j) * 33 + pixl];
                    __half h1 = s[(c8 + 2 * j + 1) * 33 + pixl];
                    pacc[2 * j]     += __half2float(h0);
                    pacc[2 * j + 1] += __half2float(h1);
                    __half2 hv = __halves2half2(h0, h1);
                    pk[j] = *(uint32_t*)&hv;
                }
                *(uint4*)(g_xT + (((size_t)b * H_ + y) * W_ + p0 + pixl) * C_ + c0 + c8) =
                    make_uint4(pk[0], pk[1], pk[2], pk[3]);
            }
            __syncwarp();   // protect smem tile reuse next iteration

            #pragma unroll
            for (int j = 0; j < 8; j++)
                atomicAdd(&g_pooled[b * C_ + c0 + c8 + j], pacc[j]);
        }
    }
    global_bar();

    // ========== phase 1: attention + agg_b (CTAs 0..31) ==========
    {
        float* sp = (float*)smem;          // 128
        float* sh = sp + 128;              // 4
        float* sa = sh + 4;                // 4
        const bool act = (cid < B_);
        const int b = cid;
        if (act && tid < 128)
            sp[tid] = g_pooled[b * C_ + tid] * (1.0f / (H_ * W_));
        __syncthreads();
        if (act && wid < 4) {
            float p = 0.f;
            #pragma unroll
            for (int c = lane; c < C_; c += 32) p += sp[c] * w1[wid * C_ + c];
            #pragma unroll
            for (int off = 16; off > 0; off >>= 1) p += __shfl_down_sync(0xffffffffu, p, off);
            if (lane == 0) sh[wid] = fmaxf(p + b1[wid], 0.f);
        }
        __syncthreads();
        if (act && tid == 0) {
            float lg[K_];
            #pragma unroll
            for (int j = 0; j < K_; j++) {
                float t = b2[j];
                #pragma unroll
                for (int k = 0; k < K_; k++) t += sh[k] * w2[j * K_ + k];
                lg[j] = t;
            }
            float m = lg[0];
            #pragma unroll
            for (int j = 1; j < K_; j++) m = fmaxf(m, lg[j]);
            float den = 0.f, e[K_];
            #pragma unroll
            for (int j = 0; j < K_; j++) { e[j] = __expf(lg[j] - m); den += e[j]; }
            #pragma unroll
            for (int j = 0; j < K_; j++) {
                sa[j] = e[j] / den;
                g_attn[b * K_ + j] = sa[j];
            }
        }
        __syncthreads();
        if (act && tid < 128) {
            float bb = 0.f;
            #pragma unroll
            for (int k = 0; k < K_; k++) bb += sa[k] * bias[k * O_ + tid];
            g_aggb[b * O_ + tid] = bb;
        }
    }
    global_bar();

    // ========== phase 2: weight aggregation -> fp16 [b][rs][o][c] ==========
    {
        int idx = cid * 512 + tid;               // 75776 threads, 65536 items
        if (idx < 65536) {
            int bg = idx >> 14;
            int oc = idx & 16383;
            int o = oc >> 7, c = oc & 127;
            int b0 = bg * 8;
            float w[K_][RS_];
            #pragma unroll
            for (int k = 0; k < K_; k++) {
                const float* p = weight + ((size_t)(k * O_ + o) * C_ + c) * RS_;
                #pragma unroll
                for (int rs = 0; rs < RS_; rs++) w[k][rs] = p[rs];
            }
            #pragma unroll
            for (int bb = 0; bb < 8; bb++) {
                int b = b0 + bb;
                float a0 = g_attn[b * K_ + 0], a1 = g_attn[b * K_ + 1];
                float a2 = g_attn[b * K_ + 2], a3 = g_attn[b * K_ + 3];
                #pragma unroll
                for (int rs = 0; rs < RS_; rs++) {
                    float s = a0 * w[0][rs] + a1 * w[1][rs] + a2 * w[2][rs] + a3 * w[3][rs];
                    g_aggw16[(((size_t)b * RS_ + rs) * O_ + o) * C_ + c] = __float2half_rn(s);
                }
            }
        }
    }
    global_bar();

    // ========== phase 3: persistent HMMA conv (R7 engine) ==========
    const int wm = wid & 1;
    const int wq = wid >> 1;
    const int h  = wq >> 2;
    const int nb = (wq & 3) * 32;

    const int lAr = lane & 15;
    const int lAk = (lane >> 4) * 16;
    const int lg  = lane >> 3;
    const int lr  = lane & 7;
    const int lBrow = (lg >> 1) * 8 + lr;
    const int lBk   = (lg & 1) * 16;

    const int cbase = TILES2 / NCTA;
    const int crem  = TILES2 % NCTA;
    const int cnt   = cbase + (cid < crem ? 1 : 0);
    const int start = cid * cbase + (cid < crem ? cid : crem);
    if (cnt == 0) return;

    int apar = 0;

    for (int t = start; t < start + cnt; t++) {
        const int b = t >> 6, yp = t & 63, y0 = yp * 2;
        const bool cold = (t == start) || (yp == 0);

        if (cold) {
            CP_WAIT(0);
            __syncthreads();
            apar = 0;
            stage_Brow(sb, b, y0 - 1, tid);
            stage_Brow(sb, b, y0,     tid);
            stage_Brow(sb, b, y0 + 1, tid);
            stage_Brow(sb, b, y0 + 2, tid);
            stage_A(sb, 0, g_aggw16 + ((size_t)b * RS_ + 0) * O_ * C_, tid);
            CP_COMMIT();
            stage_A(sb, 1, g_aggw16 + ((size_t)b * RS_ + 1) * O_ * C_, tid);
            CP_COMMIT();
        }

        float acc[4][4][4];
        #pragma unroll
        for (int mt = 0; mt < 4; mt++)
            #pragma unroll
            for (int nt = 0; nt < 4; nt++)
                #pragma unroll
                for (int j = 0; j < 4; j++) acc[mt][nt][j] = 0.f;

        for (int rs = 0; rs < 9; rs++) {
            CP_WAIT(1);
            __syncthreads();

            const int abuf = (rs + apar) & 1;
            const int r = rs / 3, s = rs - 3 * r;
            const int ry = y0 - 1 + r + h;
            const uint32_t Bbase = sb + SM_B_OFF + (uint32_t)((ry + 4) & 3) * B_ROW
                                 + (nb + lBrow + s) * A_STRIDE + lBk;
            const uint32_t Abase = sb + abuf * A_BYTES + (wm * 64 + lAr) * A_STRIDE + lAk;

            uint32_t bf[2][4][2];
            uint32_t af[2][4];
            {
                uint32_t tt[4];
                ldmat_x4(tt, Bbase);
                bf[0][0][0] = tt[0]; bf[0][0][1] = tt[1];
                bf[0][1][0] = tt[2]; bf[0][1][1] = tt[3];
                ldmat_x4(tt, Bbase + 16 * A_STRIDE);
                bf[0][2][0] = tt[0]; bf[0][2][1] = tt[1];
                bf[0][3][0] = tt[2]; bf[0][3][1] = tt[3];
            }
            ldmat_x4(af[0], Abase);

            #pragma unroll
            for (int kc = 0; kc < 8; kc++) {
                if (kc < 7) {
                    uint32_t tt[4];
                    ldmat_x4(tt, Bbase + (kc + 1) * 32);
                    bf[(kc + 1) & 1][0][0] = tt[0]; bf[(kc + 1) & 1][0][1] = tt[1];
                    bf[(kc + 1) & 1][1][0] = tt[2]; bf[(kc + 1) & 1][1][1] = tt[3];
                    ldmat_x4(tt, Bbase + 16 * A_STRIDE + (kc + 1) * 32);
                    bf[(kc + 1) & 1][2][0] = tt[0]; bf[(kc + 1) & 1][2][1] = tt[1];
                    bf[(kc + 1) & 1][3][0] = tt[2]; bf[(kc + 1) & 1][3][1] = tt[3];
                }
                #pragma unroll
                for (int mt = 0; mt < 4; mt++) {
                    int nmt = (mt + 1) & 3;
                    int nkc = (mt == 3) ? kc + 1 : kc;
                    if (nkc < 8)
                        ldmat_x4(af[(mt + 1) & 1], Abase + nmt * 16 * A_STRIDE + nkc * 32);
                    #pragma unroll
                    for (int nt = 0; nt < 4; nt++)
                        mma16816(acc[mt][nt], af[mt & 1], bf[kc & 1][nt]);
                }
            }
            __syncthreads();

            {
                int nrs = rs + 2;
                int crs = (nrs < 9) ? nrs : nrs - 9;
                stage_A(sb, (rs + apar) & 1,
                        g_aggw16 + ((size_t)b * RS_ + crs) * O_ * C_, tid);
                if (rs == 2) stage_Brow(sb, b, y0 + 3, tid);
                if (rs == 5) stage_Brow(sb, b, y0 + 4, tid);
                CP_COMMIT();
            }
        }
        apar ^= 1;

        // ---- epilogue ----
        const int g = lane >> 2, t4 = lane & 3;
        const int yout = y0 + h;
        #pragma unroll
        for (int mt = 0; mt < 4; mt++) {
            int o_lo = wm * 64 + mt * 16 + g;
            float b_lo = g_aggb[b * O_ + o_lo];
            float b_hi = g_aggb[b * O_ + o_lo + 8];
            float* p_lo = out + ((size_t)(b * O_ + o_lo) * H_ + yout) * W_;
            float* p_hi = p_lo + (size_t)8 * H_ * W_;
            #pragma unroll
            for (int nt = 0; nt < 4; nt++) {
                int xp = nb + nt * 8 + t4 * 2;
                float2 vlo = make_float2(acc[mt][nt][0] + b_lo, acc[mt][nt][1] + b_lo);
                float2 vhi = make_float2(acc[mt][nt][2] + b_hi, acc[mt][nt][3] + b_hi);
                *(float2*)(p_lo + xp) = vlo;
                *(float2*)(p_hi + xp) = vhi;
            }
        }
    }
    CP_WAIT(0);
}

// ---------------- launch ----------------
extern "C" void kernel_launch(void* const* d_in, const int* in_sizes, int n_in,
                              void* d_out, int out_size) {
    const float* x      = (const float*)d_in[0];
    const float* att_w1 = (const float*)d_in[1];
    const float* att_b1 = (const float*)d_in[2];
    const float* att_w2 = (const float*)d_in[3];
    const float* att_b2 = (const float*)d_in[4];
    const float* weight = (const float*)d_in[5];
    const float* bias   = (const float*)d_in[6];
    float* out = (float*)d_out;

    cudaFuncSetAttribute(mega, cudaFuncAttributeMaxDynamicSharedMemorySize, SMEM_CONV);
    mega<<<NCTA, 512, SMEM_CONV>>>(x, att_w1, att_b1, att_w2, att_b2, bias, weight, out);
}

// round 15
// speedup vs baseline: 1.8977x; 1.8977x over previous
#include <cuda_runtime.h>
#include <cuda_fp16.h>
#include <cstdint>

#define B_ 32
#define C_ 128
#define H_ 128
#define W_ 128
#define K_ 4
#define O_ 128
#define RS_ 9
#define NCTA 152
#define TILES2 (B_ * (H_ / 2))   // 2048 two-row tiles

// ---------------- scratch ----------------
__device__ float  g_poolrow[(size_t)B_ * H_ * C_];
__device__ float  g_attn[B_ * K_];
__device__ float  g_aggb[B_ * O_];
__device__ __half g_aggw16[(size_t)B_ * RS_ * O_ * C_];      // [b][rs][o][c]
__device__ __half g_xT[(size_t)B_ * H_ * W_ * C_];           // [b][y][p][c] NHWC fp16

// ---------------- helpers ----------------
__device__ __forceinline__ uint32_t smem_u32(const void* p) {
    uint32_t a;
    asm("{ .reg .u64 t; cvta.to.shared.u64 t, %1; cvt.u32.u64 %0, t; }" : "=r"(a) : "l"(p));
    return a;
}
__device__ __forceinline__ void cp16(uint32_t dst, const void* src, int srcsize) {
    asm volatile("cp.async.cg.shared.global [%0], [%1], 16, %2;"
                 :: "r"(dst), "l"(src), "r"(srcsize) : "memory");
}
#define CP_COMMIT() asm volatile("cp.async.commit_group;" ::: "memory")
#define CP_WAIT(n)  asm volatile("cp.async.wait_group %0;" :: "n"(n) : "memory")

__device__ __forceinline__ void ldmat_x4(uint32_t* r, uint32_t addr) {
    asm volatile("ldmatrix.sync.aligned.m8n8.x4.shared.b16 {%0,%1,%2,%3}, [%4];"
                 : "=r"(r[0]), "=r"(r[1]), "=r"(r[2]), "=r"(r[3]) : "r"(addr));
}
__device__ __forceinline__ void mma16816(float* c, const uint32_t* a, const uint32_t* b) {
    asm volatile("mma.sync.aligned.m16n8k16.row.col.f32.f16.f16.f32 "
                 "{%0,%1,%2,%3}, {%4,%5,%6,%7}, {%8,%9}, {%0,%1,%2,%3};"
                 : "+f"(c[0]), "+f"(c[1]), "+f"(c[2]), "+f"(c[3])
                 : "r"(a[0]), "r"(a[1]), "r"(a[2]), "r"(a[3]), "r"(b[0]), "r"(b[1]));
}

// ---------------- 1) NCHW fp32 -> NHWC fp16 transpose + row pooling (R7 version) ----------------
__global__ __launch_bounds__(256) void xT_kernel(const float* __restrict__ x) {
    __shared__ __half sA[8][64 * 33];
    __shared__ float sPool[128];
    int tid = threadIdx.x, w = tid >> 5, l = tid & 31;
    int by = blockIdx.x;
    int b = by >> 7, y = by & 127;
    int c0 = (w & 1) * 64, p0 = (w >> 1) * 32;
    if (tid < 128) sPool[tid] = 0.f;
    __syncthreads();
    __half* s = sA[w];
    #pragma unroll 8
    for (int i = 0; i < 64; i++) {
        float v = x[(((size_t)b * C_ + c0 + i) * H_ + y) * W_ + p0 + l];
        s[i * 33 + l] = __float2half_rn(v);
    }
    __syncwarp();
    const int c8 = (l & 7) * 8;
    const int pxg = l >> 3;
    float pacc[8];
    #pragma unroll
    for (int j = 0; j < 8; j++) pacc[j] = 0.f;
    #pragma unroll
    for (int i = 0; i < 8; i++) {
        int pixl = pxg + 4 * i;
        uint32_t pk[4];
        #pragma unroll
        for (int j = 0; j < 4; j++) {
            __half h0 = s[(c8 + 2 * j) * 33 + pixl];
            __half h1 = s[(c8 + 2 * j + 1) * 33 + pixl];
            pacc[2 * j]     += __half2float(h0);
            pacc[2 * j + 1] += __half2float(h1);
            __half2 hv = __halves2half2(h0, h1);
            pk[j] = *(uint32_t*)&hv;
        }
        *(uint4*)(g_xT + (((size_t)b * H_ + y) * W_ + p0 + pixl) * C_ + c0 + c8) =
            make_uint4(pk[0], pk[1], pk[2], pk[3]);
    }
    #pragma unroll
    for (int j = 0; j < 8; j++) atomicAdd(&sPool[c0 + c8 + j], pacc[j]);
    __syncthreads();
    if (tid < 128)
        g_poolrow[((size_t)b * H_ + y) * C_ + tid] = sPool[tid];
}

// ---------------- 2) fused pooling finish + attention + agg_b ----------------
__global__ __launch_bounds__(128) void attn2_kernel(const float* __restrict__ w1,
                                                    const float* __restrict__ b1,
                                                    const float* __restrict__ w2,
                                                    const float* __restrict__ b2,
                                                    const float* __restrict__ bias) {
    __shared__ float sp[128];
    __shared__ float sh[K_];
    __shared__ float sa[K_];
    int b = blockIdx.x, tid = threadIdx.x, lane = tid & 31, wid = tid >> 5;

    float s = 0.f;
    const float* pr = g_poolrow + (size_t)b * H_ * C_ + tid;
    #pragma unroll 8
    for (int y = 0; y < H_; y++) s += pr[(size_t)y * C_];
    sp[tid] = s * (1.0f / (H_ * W_));
    __syncthreads();

    {
        float p = 0.f;
        #pragma unroll
        for (int c = lane; c < C_; c += 32) p += sp[c] * w1[wid * C_ + c];
        #pragma unroll
        for (int off = 16; off > 0; off >>= 1) p += __shfl_down_sync(0xffffffffu, p, off);
        if (lane == 0) sh[wid] = fmaxf(p + b1[wid], 0.f);
    }
    __syncthreads();
    if (tid == 0) {
        float lg[K_];
        #pragma unroll
        for (int j = 0; j < K_; j++) {
            float t = b2[j];
            #pragma unroll
            for (int k = 0; k < K_; k++) t += sh[k] * w2[j * K_ + k];
            lg[j] = t;
        }
        float m = lg[0];
        #pragma unroll
        for (int j = 1; j < K_; j++) m = fmaxf(m, lg[j]);
        float den = 0.f, e[K_];
        #pragma unroll
        for (int j = 0; j < K_; j++) { e[j] = __expf(lg[j] - m); den += e[j]; }
        #pragma unroll
        for (int j = 0; j < K_; j++) {
            sa[j] = e[j] / den;
            g_attn[b * K_ + j] = sa[j];
        }
    }
    __syncthreads();
    float bb = 0.f;
    #pragma unroll
    for (int k = 0; k < K_; k++) bb += sa[k] * bias[k * O_ + tid];
    g_aggb[b * O_ + tid] = bb;
}

// ---------------- 3) weight aggregation v2 -> fp16 [b][rs][o][c] ----------------
__global__ __launch_bounds__(256) void aggw16_kernel(const float* __restrict__ weight) {
    int idx = blockIdx.x * 256 + threadIdx.x;   // 16384 = O_*C_
    int o = idx >> 7, c = idx & 127;
    int b0 = blockIdx.y * 8;
    float w[K_][RS_];
    #pragma unroll
    for (int k = 0; k < K_; k++) {
        const float* p = weight + ((size_t)(k * O_ + o) * C_ + c) * RS_;
        #pragma unroll
        for (int rs = 0; rs < RS_; rs++) w[k][rs] = p[rs];
    }
    #pragma unroll
    for (int bb = 0; bb < 8; bb++) {
        int b = b0 + bb;
        float a0 = g_attn[b * K_ + 0], a1 = g_attn[b * K_ + 1];
        float a2 = g_attn[b * K_ + 2], a3 = g_attn[b * K_ + 3];
        #pragma unroll
        for (int rs = 0; rs < RS_; rs++) {
            float s = a0 * w[0][rs] + a1 * w[1][rs] + a2 * w[2][rs] + a3 * w[3][rs];
            g_aggw16[(((size_t)b * RS_ + rs) * O_ + o) * C_ + c] = __float2half_rn(s);
        }
    }
}

// ---------------- 4) persistent HMMA conv (R7 best-measured variant, untouched) ----------------
#define A_STRIDE 272
#define A_BYTES  (128 * A_STRIDE)            // 34816
#define SM_B_OFF (2 * A_BYTES)               // 69632
#define B_ROW    (130 * A_STRIDE)            // 35360
#define SMEM_CONV (SM_B_OFF + 4 * B_ROW)     // 211072

__device__ __forceinline__ void stage_A(uint32_t sb, int buf, const __half* __restrict__ asrc,
                                        int tid) {
    uint32_t dst = sb + buf * A_BYTES;
    #pragma unroll
    for (int k = 0; k < 4; k++) {
        int i = tid + k * 512;
        int o = i >> 4, ch = i & 15;
        cp16(dst + o * A_STRIDE + ch * 16, asrc + (size_t)o * C_ + ch * 8, 16);
    }
}
__device__ __forceinline__ void stage_Brow(uint32_t sb, int b, int ry, int tid) {
    int slot = (ry + 4) & 3;
    bool rok = (ry >= 0) & (ry < H_);
    const __half* rbase = g_xT + ((size_t)b * H_ + (rok ? ry : 0)) * W_ * C_;
    uint32_t dst = sb + SM_B_OFF + slot * B_ROW;
    for (int i = tid; i < 2080; i += 512) {
        int p = i >> 4, ch = i & 15;
        int px = p - 1;
        bool ok = rok & (px >= 0) & (px < W_);
        cp16(dst + p * A_STRIDE + ch * 16, rbase + (size_t)(ok ? px : 0) * C_ + ch * 8,
             ok ? 16 : 0);
    }
}

__global__ void __launch_bounds__(512, 1) conv_hmma(float* __restrict__ out) {
    extern __shared__ char smem[];
    const uint32_t sb = smem_u32(smem);
    const int tid = threadIdx.x, lane = tid & 31, wid = tid >> 5;   // 16 warps
    const int wm = wid & 1;                    // o half (0/64)
    const int wq = wid >> 1;                   // 0..7
    const int h  = wq >> 2;                    // output row within pair
    const int nb = (wq & 3) * 32;              // pixel quarter

    const int lAr = lane & 15;
    const int lAk = (lane >> 4) * 16;
    const int lg  = lane >> 3;
    const int lr  = lane & 7;
    const int lBrow = (lg >> 1) * 8 + lr;
    const int lBk   = (lg & 1) * 16;

    const int cbase = TILES2 / NCTA;
    const int crem  = TILES2 % NCTA;
    const int cid   = blockIdx.x;
    const int cnt   = cbase + (cid < crem ? 1 : 0);
    const int start = cid * cbase + (cid < crem ? cid : crem);
    if (cnt == 0) return;

    int apar = 0;

    for (int t = start; t < start + cnt; t++) {
        const int b = t >> 6, yp = t & 63, y0 = yp * 2;
        const bool cold = (t == start) || (yp == 0);

        if (cold) {
            CP_WAIT(0);
            __syncthreads();
            apar = 0;
            stage_Brow(sb, b, y0 - 1, tid);
            stage_Brow(sb, b, y0,     tid);
            stage_Brow(sb, b, y0 + 1, tid);
            stage_Brow(sb, b, y0 + 2, tid);
            stage_A(sb, 0, g_aggw16 + ((size_t)b * RS_ + 0) * O_ * C_, tid);
            CP_COMMIT();
            stage_A(sb, 1, g_aggw16 + ((size_t)b * RS_ + 1) * O_ * C_, tid);
            CP_COMMIT();
        }

        float acc[4][4][4];
        #pragma unroll
        for (int mt = 0; mt < 4; mt++)
            #pragma unroll
            for (int nt = 0; nt < 4; nt++)
                #pragma unroll
                for (int j = 0; j < 4; j++) acc[mt][nt][j] = 0.f;

        for (int rs = 0; rs < 9; rs++) {
            CP_WAIT(1);
            __syncthreads();

            const int abuf = (rs + apar) & 1;
            const int r = rs / 3, s = rs - 3 * r;
            const int ry = y0 - 1 + r + h;
            const uint32_t Bbase = sb + SM_B_OFF + (uint32_t)((ry + 4) & 3) * B_ROW
                                 + (nb + lBrow + s) * A_STRIDE + lBk;
            const uint32_t Abase = sb + abuf * A_BYTES + (wm * 64 + lAr) * A_STRIDE + lAk;

            uint32_t bf[2][4][2];
            uint32_t af[2][4];
            {
                uint32_t tt[4];
                ldmat_x4(tt, Bbase);
                bf[0][0][0] = tt[0]; bf[0][0][1] = tt[1];
                bf[0][1][0] = tt[2]; bf[0][1][1] = tt[3];
                ldmat_x4(tt, Bbase + 16 * A_STRIDE);
                bf[0][2][0] = tt[0]; bf[0][2][1] = tt[1];
                bf[0][3][0] = tt[2]; bf[0][3][1] = tt[3];
            }
            ldmat_x4(af[0], Abase);

            #pragma unroll
            for (int kc = 0; kc < 8; kc++) {
                if (kc < 7) {
                    uint32_t tt[4];
                    ldmat_x4(tt, Bbase + (kc + 1) * 32);
                    bf[(kc + 1) & 1][0][0] = tt[0]; bf[(kc + 1) & 1][0][1] = tt[1];
                    bf[(kc + 1) & 1][1][0] = tt[2]; bf[(kc + 1) & 1][1][1] = tt[3];
                    ldmat_x4(tt, Bbase + 16 * A_STRIDE + (kc + 1) * 32);
                    bf[(kc + 1) & 1][2][0] = tt[0]; bf[(kc + 1) & 1][2][1] = tt[1];
                    bf[(kc + 1) & 1][3][0] = tt[2]; bf[(kc + 1) & 1][3][1] = tt[3];
                }
                #pragma unroll
                for (int mt = 0; mt < 4; mt++) {
                    int nmt = (mt + 1) & 3;
                    int nkc = (mt == 3) ? kc + 1 : kc;
                    if (nkc < 8)
                        ldmat_x4(af[(mt + 1) & 1], Abase + nmt * 16 * A_STRIDE + nkc * 32);
                    #pragma unroll
                    for (int nt = 0; nt < 4; nt++)
                        mma16816(acc[mt][nt], af[mt & 1], bf[kc & 1][nt]);
                }
            }
            __syncthreads();

            {
                int nrs = rs + 2;
                int crs = (nrs < 9) ? nrs : nrs - 9;
                stage_A(sb, (rs + apar) & 1,
                        g_aggw16 + ((size_t)b * RS_ + crs) * O_ * C_, tid);
                if (rs == 2) stage_Brow(sb, b, y0 + 3, tid);
                if (rs == 5) stage_Brow(sb, b, y0 + 4, tid);
                CP_COMMIT();
            }
        }
        apar ^= 1;

        // ---- epilogue ----
        const int g = lane >> 2, t4 = lane & 3;
        const int yout = y0 + h;
        #pragma unroll
        for (int mt = 0; mt < 4; mt++) {
            int o_lo = wm * 64 + mt * 16 + g;
            float b_lo = g_aggb[b * O_ + o_lo];
            float b_hi = g_aggb[b * O_ + o_lo + 8];
            float* p_lo = out + ((size_t)(b * O_ + o_lo) * H_ + yout) * W_;
            float* p_hi = p_lo + (size_t)8 * H_ * W_;
            #pragma unroll
            for (int nt = 0; nt < 4; nt++) {
                int xp = nb + nt * 8 + t4 * 2;
                float2 vlo = make_float2(acc[mt][nt][0] + b_lo, acc[mt][nt][1] + b_lo);
                float2 vhi = make_float2(acc[mt][nt][2] + b_hi, acc[mt][nt][3] + b_hi);
                *(float2*)(p_lo + xp) = vlo;
                *(float2*)(p_hi + xp) = vhi;
            }
        }
    }
    CP_WAIT(0);
}

// ---------------- launch ----------------
extern "C" void kernel_launch(void* const* d_in, const int* in_sizes, int n_in,
                              void* d_out, int out_size) {
    const float* x      = (const float*)d_in[0];
    const float* att_w1 = (const float*)d_in[1];
    const float* att_b1 = (const float*)d_in[2];
    const float* att_w2 = (const float*)d_in[3];
    const float* att_b2 = (const float*)d_in[4];
    const float* weight = (const float*)d_in[5];
    const float* bias   = (const float*)d_in[6];
    float* out = (float*)d_out;

    cudaFuncSetAttribute(conv_hmma, cudaFuncAttributeMaxDynamicSharedMemorySize, SMEM_CONV);

    xT_kernel<<<B_ * H_, 256>>>(x);
    attn2_kernel<<<B_, 128>>>(att_w1, att_b1, att_w2, att_b2, bias);
    aggw16_kernel<<<dim3(64, 4), 256>>>(weight);
    conv_hmma<<<NCTA, 512, SMEM_CONV>>>(out);
}